// round 17
// baseline (speedup 1.0000x reference)
#include <cuda_runtime.h>
#include <cstdint>

// ============================================================================
// Fused int8 fake-quant conv3x3(5->10) + conv3x3(10->10), pow2 scales.
// Bit-exact integer arithmetic. R17: SPLIT into two kernels to break the
// occupancy cap (fused needed 80 regs -> stuck at 3 blocks/SM).
//   K1 conv1: dp4a, 4-px strips (256 tasks exact), ~60 regs, occ 4;
//             y written ONCE globally (no halo recompute) as:
//               g_yA[r][c] uint2 {ch0-3, ch4-7}
//               g_yB[r][c] uint2 {ch89(r,r+1), ch89(r+2)|garbage}
//             staged in smem + coalesced copy; cross-tile ch89 bytes via
//             direct single-writer STG.16.
//   K2 conv2: R16 Phase C verbatim with LDG.64 fragment loads from g_yA/g_yB.
// ============================================================================

// y arrays: 32 images x 516 rows (pad; reads reach row 513) x 512 cols.
// Zero-initialized by CUDA at module load (reads of never-written pads are 0).
__device__ uint2 g_yA[32u * 516u * 512u];
__device__ uint2 g_yB[32u * 516u * 512u];

__device__ float g_consts[4];       // inv_s_in, m1, m2, s_o2
__device__ int   g_b1i[10];
__device__ int   g_b2i16[16];
__device__ unsigned g_w1a[90];      // [oc*9+tap]: ch0-3 packed
__device__ unsigned g_w1b[30];      // [oc*3+ky]:  [w4_kx0,w4_kx1,w4_kx2,0]
__device__ unsigned g_b2t[192];     // IMMA B frags [kr(6)][lane(32)], oc0-7
__device__ unsigned g_w89q[48];     // oc8/9 dp4a words [kr(6)][oc2(2)][quad(4)]

__device__ __forceinline__ int clampq(float v) {
    int q = __float2int_rn(v);
    return max(-128, min(127, q));
}
__device__ __forceinline__ unsigned q8b(float v) {
    unsigned r;
    asm("cvt.rni.sat.s8.f32 %0, %1;" : "=r"(r) : "f"(v));
    return r;
}
__device__ __forceinline__ float requant(int acc, float m, float so) {
    const float t = (float)acc * m;
    unsigned q;
    asm("cvt.rni.sat.s8.f32 %0, %1;" : "=r"(q) : "f"(t));
    float f;
    asm("cvt.rn.f32.s8 %0, %1;" : "=f"(f) : "r"(q));
    return f * so;
}
__device__ __forceinline__ void imma16832(int* d,
    unsigned a0, unsigned a1, unsigned a2, unsigned a3,
    unsigned b0, unsigned b1) {
    asm volatile(
        "mma.sync.aligned.m16n8k32.row.col.s32.s8.s8.s32 "
        "{%0,%1,%2,%3}, {%4,%5,%6,%7}, {%8,%9}, {%0,%1,%2,%3};\n"
        : "+r"(d[0]), "+r"(d[1]), "+r"(d[2]), "+r"(d[3])
        : "r"(a0), "r"(a1), "r"(a2), "r"(a3), "r"(b0), "r"(b1));
}

// conv2 weight byte for IMMA slot (s, j, quad), byte b, output channel n.
// quads 0-2: tap (ky=s, kx=quad), ch = j*4+b  (yA word pair)
// quad 3, j0: yB.lo bytes (ch8 ky0, ch9 ky0, ch8 ky1, ch9 ky1), kx=s
// quad 3, j1: yB.hi bytes (ch8 ky2, ch9 ky2, 0, 0), kx=s
__device__ __forceinline__ int getW2s(const float* w2, float sw2,
                                      int n, int s, int j, int quad, int b) {
    if (quad < 3) {
        const int ky = s, kx = quad, ch = j * 4 + b;
        return clampq(w2[((n * 10 + ch) * 3 + ky) * 3 + kx] / sw2);
    }
    if (j == 0) {
        const int ky = b >> 1, ch = 8 + (b & 1);
        return clampq(w2[((n * 10 + ch) * 3 + ky) * 3 + s] / sw2);
    }
    if (b >= 2) return 0;
    return clampq(w2[((n * 10 + 8 + b) * 3 + 2) * 3 + s] / sw2);
}

__global__ void prep_kernel(const float* __restrict__ w1, const float* __restrict__ b1,
                            const float* __restrict__ w2, const float* __restrict__ b2,
                            const float* __restrict__ s_in, const float* __restrict__ s_w1,
                            const float* __restrict__ s_o1, const float* __restrict__ s_w2,
                            const float* __restrict__ s_o2) {
    const int t = threadIdx.x;
    const float si = s_in[0], sw1 = s_w1[0], so1 = s_o1[0], sw2 = s_w2[0], so2 = s_o2[0];
    if (t == 0) {
        g_consts[0] = 1.0f / si;
        g_consts[1] = (si * sw1) / so1;
        g_consts[2] = (so1 * sw2) / so2;
        g_consts[3] = so2;
    }
    if (t < 10) g_b1i[t] = clampq(b1[t] / (si * sw1));
    if (t < 16) g_b2i16[t] = (t < 10) ? clampq(b2[t] / (so1 * sw2)) : 0;
    if (t < 90) {
        const int oc = t / 9, tap = t % 9;
        const int ky = tap / 3, kx = tap % 3;
        unsigned a = 0;
        #pragma unroll
        for (int c = 0; c < 4; c++) {
            int q = clampq(w1[((oc * 5 + c) * 3 + ky) * 3 + kx] / sw1);
            a |= ((unsigned)(q & 0xFF)) << (8 * c);
        }
        g_w1a[t] = a;
    }
    if (t < 30) {
        const int oc = t / 3, ky = t % 3;
        unsigned b = 0;
        #pragma unroll
        for (int kx = 0; kx < 3; kx++) {
            int q = clampq(w1[((oc * 5 + 4) * 3 + ky) * 3 + kx] / sw1);
            b |= ((unsigned)(q & 0xFF)) << (8 * kx);
        }
        g_w1b[t] = b;
    }
    for (int idx = t; idx < 192; idx += blockDim.x) {
        const int kr = idx >> 5, lane = idx & 31;
        const int s = kr >> 1, j = kr & 1;
        const int quad = lane & 3, n = lane >> 2;
        unsigned v = 0;
        #pragma unroll
        for (int b = 0; b < 4; b++)
            v |= ((unsigned)(getW2s(w2, sw2, n, s, j, quad, b) & 0xFF)) << (8 * b);
        g_b2t[idx] = v;
    }
    for (int idx = t; idx < 48; idx += blockDim.x) {
        const int kr = idx >> 3, oc2 = (idx >> 2) & 1, quad = idx & 3;
        const int s = kr >> 1, j = kr & 1;
        unsigned v = 0;
        #pragma unroll
        for (int b = 0; b < 4; b++)
            v |= ((unsigned)(getW2s(w2, sw2, 8 + oc2, s, j, quad, b) & 0xFF)) << (8 * b);
        g_w89q[idx] = v;
    }
}

// ===================== K1: conv1 (x -> y), occ 4 =====================
__global__ __launch_bounds__(256, 4)
void conv1_kernel(const float* __restrict__ x) {
    __shared__ __align__(16) unsigned xs4[34][40];   // x ch0-3; 160B rows
    __shared__ __align__(16) unsigned xs1w[34][10];  // x ch4 byte plane
    __shared__ __align__(16) uint2 ysA_s[32][32];
    __shared__ __align__(16) uint2 ysB_s[32][32];
    __shared__ unsigned w1a[90], w1b[30];
    __shared__ int b1s[10];
    __shared__ float cs[2];

    const int tid = threadIdx.x;
    const int n  = blockIdx.z;
    const int ty = blockIdx.y * 32;
    const int tx = blockIdx.x * 32;

    if (tid < 90) w1a[tid] = g_w1a[tid];
    if (tid >= 96 && tid < 126) w1b[tid - 96] = g_w1b[tid - 96];
    if (tid >= 128 && tid < 138) b1s[tid - 128] = g_b1i[tid - 128];
    if (tid >= 140 && tid < 142) cs[tid - 140] = g_consts[tid - 140];
    __syncthreads();
    const float inv_s_in = cs[0], m1 = cs[1];

    // ---- Phase A: load + quantize x (34 rows x 36 cols, 5 ch) ----
    const float* xb = x + (size_t)n * 1310720u;
    #pragma unroll
    for (int it = 0; it < 2; it++) {
        const int s = tid + it * 256;
        if (s < 306) {
            const int r = s / 9, c4 = s % 9, c = c4 * 4;
            const int gy = ty + r, gx = tx + c;
            float4 v0, v1, v2, v3, v4;
            if (gy < 512 && gx < 512) {
                const float* px = xb + (size_t)gy * 512 + gx;
                v0 = *(const float4*)px;
                v1 = *(const float4*)(px + 262144);
                v2 = *(const float4*)(px + 524288);
                v3 = *(const float4*)(px + 786432);
                v4 = *(const float4*)(px + 1048576);
            } else {
                v0 = v1 = v2 = v3 = v4 = make_float4(0.f, 0.f, 0.f, 0.f);
            }
            uint4 w;
            w.x = __byte_perm(__byte_perm(q8b(v0.x * inv_s_in), q8b(v1.x * inv_s_in), 0x0040),
                              __byte_perm(q8b(v2.x * inv_s_in), q8b(v3.x * inv_s_in), 0x0040), 0x5410);
            w.y = __byte_perm(__byte_perm(q8b(v0.y * inv_s_in), q8b(v1.y * inv_s_in), 0x0040),
                              __byte_perm(q8b(v2.y * inv_s_in), q8b(v3.y * inv_s_in), 0x0040), 0x5410);
            w.z = __byte_perm(__byte_perm(q8b(v0.z * inv_s_in), q8b(v1.z * inv_s_in), 0x0040),
                              __byte_perm(q8b(v2.z * inv_s_in), q8b(v3.z * inv_s_in), 0x0040), 0x5410);
            w.w = __byte_perm(__byte_perm(q8b(v0.w * inv_s_in), q8b(v1.w * inv_s_in), 0x0040),
                              __byte_perm(q8b(v2.w * inv_s_in), q8b(v3.w * inv_s_in), 0x0040), 0x5410);
            *(uint4*)&xs4[r][c] = w;
            xs1w[r][c4] = __byte_perm(__byte_perm(q8b(v4.x * inv_s_in), q8b(v4.y * inv_s_in), 0x0040),
                                      __byte_perm(q8b(v4.z * inv_s_in), q8b(v4.w * inv_s_in), 0x0040), 0x5410);
        }
    }
    __syncthreads();

    // ---- Phase B: conv1, 4-px strips, 256 tasks exact ----
    {
        const int r = tid >> 3, wi = tid & 7, cb = wi * 4;
        unsigned xv[3][6];
        #pragma unroll
        for (int ky = 0; ky < 3; ky++) {
            const uint2* rp = (const uint2*)&xs4[r + ky][cb];
            #pragma unroll
            for (int j = 0; j < 3; j++) {
                const uint2 t = rp[j];
                xv[ky][2 * j] = t.x; xv[ky][2 * j + 1] = t.y;
            }
        }
        unsigned win[3][4];
        const int wb = cb >> 2;
        #pragma unroll
        for (int ky = 0; ky < 3; ky++) {
            const unsigned A = xs1w[r + ky][wb];
            const unsigned B = xs1w[r + ky][wb + 1];
            win[ky][0] = A;
            win[ky][1] = __funnelshift_r(A, B, 8);
            win[ky][2] = __funnelshift_r(A, B, 16);
            win[ky][3] = __funnelshift_r(A, B, 24);
        }
        unsigned o0[4], o1[4], q8v[4];
        unsigned short hv[4];
        #pragma unroll
        for (int oc = 0; oc < 10; oc++) {
            int acc[4];
            const int bb = b1s[oc];
            #pragma unroll
            for (int i = 0; i < 4; i++) acc[i] = bb;
            #pragma unroll
            for (int ky = 0; ky < 3; ky++) {
                #pragma unroll
                for (int kx = 0; kx < 3; kx++) {
                    const int w = (int)w1a[oc * 9 + ky * 3 + kx];
                    #pragma unroll
                    for (int i = 0; i < 4; i++)
                        acc[i] = __dp4a((int)xv[ky][i + kx], w, acc[i]);
                }
                const int wbk = (int)w1b[oc * 3 + ky];
                #pragma unroll
                for (int i = 0; i < 4; i++)
                    acc[i] = __dp4a((int)win[ky][i], wbk, acc[i]);
            }
            #pragma unroll
            for (int i = 0; i < 4; i++) {
                const unsigned q = q8b((float)acc[i] * m1);
                if (oc == 0)      o0[i] = q;
                else if (oc == 1) o0[i] = __byte_perm(o0[i], q, 0x3240);
                else if (oc == 2) o0[i] = __byte_perm(o0[i], q, 0x3410);
                else if (oc == 3) o0[i] = __byte_perm(o0[i], q, 0x4210);
                else if (oc == 4) o1[i] = q;
                else if (oc == 5) o1[i] = __byte_perm(o1[i], q, 0x3240);
                else if (oc == 6) o1[i] = __byte_perm(o1[i], q, 0x3410);
                else if (oc == 7) o1[i] = __byte_perm(o1[i], q, 0x4210);
                else if (oc == 8) q8v[i] = q;
                else hv[i] = (unsigned short)((q8v[i] & 0xFFu) | ((q & 0xFFu) << 8));
            }
        }
        const size_t ibase = (size_t)n * (516u * 512u);
        #pragma unroll
        for (int i = 0; i < 4; i++) {
            const int c = cb + i;
            ysA_s[r][c] = make_uint2(o0[i], o1[i]);
            // hv(R) -> yB[R].b01, yB[R-1].b23, yB[R-2].b45
            *(unsigned short*)((unsigned char*)&ysB_s[r][c]) = hv[i];
            const int gc = tx + c;
            if (r >= 1) {
                *(unsigned short*)((unsigned char*)&ysB_s[r - 1][c] + 2) = hv[i];
            } else if (ty >= 1 && gc < 510) {
                *(unsigned short*)((unsigned char*)(g_yB + ibase + (size_t)(ty - 1) * 512 + gc) + 2) = hv[i];
            }
            if (r >= 2) {
                *(unsigned short*)((unsigned char*)&ysB_s[r - 2][c] + 4) = hv[i];
            } else if (ty + r >= 2 && gc < 510) {
                *(unsigned short*)((unsigned char*)(g_yB + ibase + (size_t)(ty + r - 2) * 512 + gc) + 4) = hv[i];
            }
        }
    }
    __syncthreads();

    // ---- Phase B2: coalesced copy smem -> gmem ----
    {
        const size_t ibase = (size_t)n * (516u * 512u);
        #pragma unroll
        for (int p = 0; p < 4; p++) {
            const int idx = tid + p * 256;      // 1024 px
            const int r = idx >> 5, c = idx & 31;
            const int gy = ty + r, gc = tx + c;
            if (gy < 510 && gc < 510)
                g_yA[ibase + (size_t)gy * 512 + gc] = ysA_s[r][c];
        }
        // yB rows 0-29 full; row 30 lo word; row 31 low short (rest comes from
        // the block below's direct writes)
        #pragma unroll
        for (int p = 0; p < 4; p++) {
            const int idx = tid + p * 256;
            if (idx < 960) {
                const int r = idx >> 5, c = idx & 31;
                const int gy = ty + r, gc = tx + c;
                if (gy < 510 && gc < 510)
                    g_yB[ibase + (size_t)gy * 512 + gc] = ysB_s[r][c];
            }
        }
        if (tid < 64) {
            const int r = 30 + (tid >> 5), c = tid & 31;
            const int gy = ty + r, gc = tx + c;
            if (gy < 510 && gc < 510) {
                unsigned char* dst = (unsigned char*)(g_yB + ibase + (size_t)gy * 512 + gc);
                if (r == 30) *(unsigned*)dst = ysB_s[r][c].x;               // b01+b23
                else         *(unsigned short*)dst = (unsigned short)(ysB_s[r][c].x & 0xFFFFu); // b01
            }
        }
    }
}

// ===================== K2: conv2 (y -> out), occ 4 =====================
__global__ __launch_bounds__(256, 4)
void conv2_kernel(float* __restrict__ out) {
    __shared__ unsigned b2t[192];
    __shared__ unsigned w89s[48];
    __shared__ int b2s16[16];
    __shared__ float cs2[2];

    const int tid = threadIdx.x;
    const int n  = blockIdx.z;
    const int ty = blockIdx.y * 32;
    const int tx = blockIdx.x * 32;

    if (tid < 192) b2t[tid] = g_b2t[tid];
    if (tid >= 192 && tid < 240) w89s[tid - 192] = g_w89q[tid - 192];
    if (tid >= 240 && tid < 256) b2s16[tid - 240] = g_b2i16[tid - 240];
    if (tid < 2) cs2[tid] = g_consts[2 + tid];
    __syncthreads();
    const float m2 = cs2[0], so2 = cs2[1];

    const int lane = tid & 31, warp = tid >> 5;
    const int quad = lane & 3, pxl = lane >> 2;
    const bool q1 = (quad & 1) != 0, q2 = (quad & 2) != 0;

    unsigned B2r[6];
    #pragma unroll
    for (int kr = 0; kr < 6; kr++) B2r[kr] = b2t[kr * 32 + lane];
    unsigned W8[6], W9[6];
    #pragma unroll
    for (int kr = 0; kr < 6; kr++) {
        W8[kr] = w89s[kr * 8 + quad];
        W9[kr] = w89s[kr * 8 + 4 + quad];
    }
    const int bA0 = b2s16[quad * 2], bA1 = b2s16[quad * 2 + 1];
    const int b89 = b2s16[8 + (quad & 1)];

    const size_t ibase = (size_t)n * (516u * 512u);
    const uint2* Abase = (quad < 3) ? (g_yA + ibase) : (g_yB + ibase);
    int off[3];
    #pragma unroll
    for (int s = 0; s < 3; s++)
        off[s] = (quad < 3) ? (s * 512 + quad) : s;

    float* ob = out + (size_t)n * 2580640u;

    #pragma unroll
    for (int k8 = 0; k8 < 8; k8++) {
        const int mt = k8 * 8 + warp;          // 64 m-tiles (16 row-pairs x 4)
        const int rp = mt >> 2, cb = (mt & 3) * 8;
        const int row0 = ty + rp * 2;
        const int c0 = tx + cb + pxl;
        const uint2* Ab = Abase + (size_t)row0 * 512 + c0;
        int d0[4] = {bA0, bA1, bA0, bA1};
        int p8r0 = 0, p9r0 = 0, p8r1 = 0, p9r1 = 0;
        #pragma unroll
        for (int s = 0; s < 3; s++) {
            const uint2 lo = Ab[off[s]];           // a0, a2
            const uint2 hi = Ab[off[s] + 512];     // a1, a3
            imma16832(d0, lo.x, hi.x, lo.y, hi.y, B2r[s * 2], B2r[s * 2 + 1]);
            p8r0 = __dp4a((int)lo.x, (int)W8[2 * s], p8r0);
            p8r0 = __dp4a((int)lo.y, (int)W8[2 * s + 1], p8r0);
            p8r1 = __dp4a((int)hi.x, (int)W8[2 * s], p8r1);
            p8r1 = __dp4a((int)hi.y, (int)W8[2 * s + 1], p8r1);
            p9r0 = __dp4a((int)lo.x, (int)W9[2 * s], p9r0);
            p9r0 = __dp4a((int)lo.y, (int)W9[2 * s + 1], p9r0);
            p9r1 = __dp4a((int)hi.x, (int)W9[2 * s], p9r1);
            p9r1 = __dp4a((int)hi.y, (int)W9[2 * s + 1], p9r1);
        }
        // 3-shfl reduce-scatter across the quad (lane q owns target t=q)
        const int s0 = q1 ? p8r0 : p9r0;
        const int s1 = q1 ? p8r1 : p9r1;
        const int k0 = (q1 ? p9r0 : p8r0) + __shfl_xor_sync(0xffffffffu, s0, 1);
        const int k1 = (q1 ? p9r1 : p8r1) + __shfl_xor_sync(0xffffffffu, s1, 1);
        const int s2 = q2 ? k0 : k1;
        const int v  = (q2 ? k1 : k0) + __shfl_xor_sync(0xffffffffu, s2, 2);

        const bool gxok = (c0 < 508);
        float* pb = ob + (size_t)row0 * 508u + c0;
        #pragma unroll
        for (int e = 0; e < 4; e++) {
            const int row = e >> 1, oc = quad * 2 + (e & 1);
            const float f = requant(d0[e], m2, so2);
            if (gxok && (row0 + row) < 508)
                pb[(size_t)oc * 258064u + (size_t)row * 508u] = f;
        }
        {
            const int row = quad >> 1, oc = 8 + (quad & 1);
            const float f = requant(v + b89, m2, so2);
            if (gxok && (row0 + row) < 508)
                pb[(size_t)oc * 258064u + (size_t)row * 508u] = f;
        }
    }
}

extern "C" void kernel_launch(void* const* d_in, const int* in_sizes, int n_in,
                              void* d_out, int out_size) {
    const float* x    = (const float*)d_in[0];
    const float* w1   = (const float*)d_in[1];
    const float* b1   = (const float*)d_in[2];
    const float* w2   = (const float*)d_in[3];
    const float* b2   = (const float*)d_in[4];
    const float* s_in = (const float*)d_in[5];
    const float* s_w1 = (const float*)d_in[6];
    const float* s_o1 = (const float*)d_in[7];
    const float* s_w2 = (const float*)d_in[8];
    const float* s_o2 = (const float*)d_in[9];

    prep_kernel<<<1, 256>>>(w1, b1, w2, b2, s_in, s_w1, s_o1, s_w2, s_o2);

    dim3 grid(16, 16, 32);
    conv1_kernel<<<grid, 256>>>(x);
    conv2_kernel<<<grid, 256>>>((float*)d_out);
}